// round 16
// baseline (speedup 1.0000x reference)
#include <cuda_runtime.h>
#include <mma.h>
#include <math.h>
#include <stdint.h>

using namespace nvcuda;

// Problem constants
#define BB   2
#define SS   2048
#define HH   8
#define HDIM 64
#define DD   512
#define WINW 64
#define SUBW 129
#define KSZ  2048
#define TT   (BB*SS)          // 4096
#define D3   (3*DD)           // 1536

// Attention tile constants (QT=64 version)
#define QT2   64
#define KW2   192
#define KSTR  68
#define PSTR2 200

// GEMM tile constants (128x128 block, BK=32, 4 warps, warp tile 64x64)
#define BKG   32
#define ASTR  36
#define BSTR  132
#define CSTR  132
#define AS_FLOATS (128 * ASTR)           // 4608
#define BS_FLOATS (BKG * BSTR)           // 4224
#define GEMM_SMEM ((2 * AS_FLOATS + 2 * BS_FLOATS) * 4)   // 70656 B

// Scratch (device globals; allocation-free)
__device__ float g_kqv[TT * D3];
__device__ float g_ctx[TT * DD];
__device__ float g_x1 [TT * KSZ];
__device__ float g_va [TT * DD];
__device__ float g_wq [DD * D3];
__device__ float g_wk [DD * KSZ];
__device__ float g_wp [KSZ * DD];
__device__ float g_ps [2 * TT * DD];     // split-K partials for proj GEMM

// ---------------------------------------------------------------------------
__device__ __forceinline__ float rtf32(float x) {
    uint32_t u;
    asm("cvt.rna.tf32.f32 %0, %1;" : "=r"(u) : "f"(x));
    return __uint_as_float(u);
}

#define CP_ASYNC16(dst_u32, src_ptr) \
    asm volatile("cp.async.cg.shared.global [%0], [%1], 16;" \
                 :: "r"(dst_u32), "l"(src_ptr))
#define CP_COMMIT()  asm volatile("cp.async.commit_group;")
#define CP_WAIT0()   asm volatile("cp.async.wait_group 0;")
#define CP_WAIT1()   asm volatile("cp.async.wait_group 1;")

// ---------------------------------------------------------------------------
// tf32 wmma GEMM: 128x128 block, 4 warps, warp tile 64x64 (4x4 frags),
// BK=32, cp.async double-buffered, occupancy 2.  (round-14 proven config)
// EPI: 0 = bias ; 1 = bias+relu (tf32 out) ; 3 = raw split-K partial
// ---------------------------------------------------------------------------
template <int EPI>
__global__ __launch_bounds__(128, 2)
void tgemm_k(const float* __restrict__ A, const float* __restrict__ Bm,
             const float* __restrict__ bias,
             float* __restrict__ C, int M, int N, int K, int lda)
{
    extern __shared__ float sm[];
    const uint32_t sbase = (uint32_t)__cvta_generic_to_shared(sm);

    const int tid    = threadIdx.x;
    const int warpId = tid >> 5;
    const int warpM  = warpId & 1;
    const int warpN  = warpId >> 1;

    const int blockN = blockIdx.x * 128;
    const int blockM = blockIdx.y * 128;
    const int kOff   = blockIdx.z * K;
    float* Cz = (EPI == 3) ? C + (size_t)blockIdx.z * M * N : C;

    wmma::fragment<wmma::accumulator, 16, 16, 8, float> acc[4][4];
    #pragma unroll
    for (int i = 0; i < 4; i++)
        #pragma unroll
        for (int j = 0; j < 4; j++) wmma::fill_fragment(acc[i][j], 0.f);

    auto loadTile = [&](int k0, int buf) {
        const uint32_t aOff = buf * AS_FLOATS;
        const uint32_t bOff = 2 * AS_FLOATS + buf * BS_FLOATS;
        #pragma unroll
        for (int p = 0; p < 8; p++) {
            const int idx = p * 128 + tid;
            const int ar  = idx >> 3;
            const int ac4 = (idx & 7) << 2;
            CP_ASYNC16(sbase + (aOff + ar * ASTR + ac4) * 4,
                       A + (size_t)(blockM + ar) * lda + kOff + k0 + ac4);
            const int br  = idx >> 5;
            const int bc4 = (idx & 31) << 2;
            CP_ASYNC16(sbase + (bOff + br * BSTR + bc4) * 4,
                       Bm + (size_t)(kOff + k0 + br) * N + blockN + bc4);
        }
    };

    const int nIter = K / BKG;
    loadTile(0, 0);
    CP_COMMIT();

    for (int i = 0; i < nIter; i++) {
        const int buf = i & 1;
        if (i + 1 < nIter) {
            loadTile((i + 1) * BKG, buf ^ 1);
            CP_COMMIT();
            CP_WAIT1();
        } else {
            CP_WAIT0();
        }
        __syncthreads();

        const float* As = sm + buf * AS_FLOATS;
        const float* Bs = sm + 2 * AS_FLOATS + buf * BS_FLOATS;
        #pragma unroll
        for (int kk = 0; kk < BKG; kk += 8) {
            wmma::fragment<wmma::matrix_a, 16, 16, 8, wmma::precision::tf32, wmma::row_major> af[4];
            wmma::fragment<wmma::matrix_b, 16, 16, 8, wmma::precision::tf32, wmma::row_major> bf[4];
            #pragma unroll
            for (int ii = 0; ii < 4; ii++)
                wmma::load_matrix_sync(af[ii],
                    As + (warpM * 64 + ii * 16) * ASTR + kk, ASTR);
            #pragma unroll
            for (int j = 0; j < 4; j++)
                wmma::load_matrix_sync(bf[j],
                    Bs + kk * BSTR + warpN * 64 + j * 16, BSTR);
            #pragma unroll
            for (int ii = 0; ii < 4; ii++)
                #pragma unroll
                for (int j = 0; j < 4; j++)
                    wmma::mma_sync(acc[ii][j], af[ii], bf[j], acc[ii][j]);
        }
        __syncthreads();
    }

    // epilogue: stage full 128x128 C tile through smem
    #pragma unroll
    for (int ii = 0; ii < 4; ii++)
        #pragma unroll
        for (int j = 0; j < 4; j++)
            wmma::store_matrix_sync(
                sm + (warpM * 64 + ii * 16) * CSTR + warpN * 64 + j * 16,
                acc[ii][j], CSTR, wmma::mem_row_major);
    __syncthreads();

    const int ec4 = (tid & 31) << 2;
    const int er0 = tid >> 5;
    float4 bi = make_float4(0.f, 0.f, 0.f, 0.f);
    if (EPI != 3)
        bi = *reinterpret_cast<const float4*>(bias + blockN + ec4);
    #pragma unroll
    for (int p = 0; p < 32; p++) {
        const int r = p * 4 + er0;
        const int grow = blockM + r;
        float4 o = *reinterpret_cast<const float4*>(sm + r * CSTR + ec4);
        o.x += bi.x; o.y += bi.y; o.z += bi.z; o.w += bi.w;
        if (EPI == 1) {
            o.x = rtf32(fmaxf(o.x, 0.f)); o.y = rtf32(fmaxf(o.y, 0.f));
            o.z = rtf32(fmaxf(o.z, 0.f)); o.w = rtf32(fmaxf(o.w, 0.f));
        }
        *reinterpret_cast<float4*>(&Cz[(size_t)grow * N + blockN + ec4]) = o;
    }
}

// ---------------------------------------------------------------------------
// Split-K reduction: out = ps[0] + ps[1] + b_proj + v
// ---------------------------------------------------------------------------
__global__ void splitk_reduce(const float* __restrict__ ps,
                              const float* __restrict__ bias,
                              const float* __restrict__ kqv,
                              float* __restrict__ out)
{
    const int i = blockIdx.x * blockDim.x + threadIdx.x;
    const int row = i / (DD / 4);
    const int c4  = (i % (DD / 4)) * 4;

    float4 a = reinterpret_cast<const float4*>(ps)[i];
    float4 b = reinterpret_cast<const float4*>(ps + (size_t)TT * DD)[i];
    float4 bi = *reinterpret_cast<const float4*>(bias + c4);
    float4 v = *reinterpret_cast<const float4*>(
        kqv + (size_t)row * D3 + 2 * DD + c4);

    float4 o;
    o.x = a.x + b.x + bi.x + v.x;
    o.y = a.y + b.y + bi.y + v.y;
    o.z = a.z + b.z + bi.z + v.z;
    o.w = a.w + b.w + bi.w + v.w;
    reinterpret_cast<float4*>(out)[i] = o;
}

// ---------------------------------------------------------------------------
// Fused tf32 rounding of all four source tensors in one launch.
// ---------------------------------------------------------------------------
#define R_VA 524288
#define R_WQ (R_VA + 196608)
#define R_WK (R_WQ + 262144)
#define R_WP (R_WK + 262144)

__global__ void tf32_round_all(const float* __restrict__ values,
                               const float* __restrict__ Wq,
                               const float* __restrict__ Wk,
                               const float* __restrict__ Wp,
                               float* __restrict__ va, float* __restrict__ wq,
                               float* __restrict__ wk, float* __restrict__ wp)
{
    const int i = blockIdx.x * blockDim.x + threadIdx.x;
    const float4* src; float4* dst; int off;
    if (i < R_VA)      { src = (const float4*)values; dst = (float4*)va; off = i; }
    else if (i < R_WQ) { src = (const float4*)Wq;     dst = (float4*)wq; off = i - R_VA; }
    else if (i < R_WK) { src = (const float4*)Wk;     dst = (float4*)wk; off = i - R_WQ; }
    else               { src = (const float4*)Wp;     dst = (float4*)wp; off = i - R_WK; }
    float4 v = src[off];
    v.x = rtf32(v.x); v.y = rtf32(v.y); v.z = rtf32(v.z); v.w = rtf32(v.w);
    dst[off] = v;
}

// ---------------------------------------------------------------------------
// LayerNorm in place on k and q columns of g_kqv.
// ---------------------------------------------------------------------------
__global__ void ln_kernel(float* __restrict__ kqv,
                          const float* __restrict__ gamma,
                          const float* __restrict__ beta)
{
    const int t   = blockIdx.x;
    const int sel = blockIdx.y;
    float* row = kqv + (size_t)t * D3 + sel * DD;
    const int tid = threadIdx.x;

    float4 v = reinterpret_cast<float4*>(row)[tid];
    float s  = v.x + v.y + v.z + v.w;
    float sq = v.x*v.x + v.y*v.y + v.z*v.z + v.w*v.w;

    #pragma unroll
    for (int o = 16; o; o >>= 1) {
        s  += __shfl_xor_sync(0xffffffffu, s,  o);
        sq += __shfl_xor_sync(0xffffffffu, sq, o);
    }
    __shared__ float rs[4], rq[4];
    if ((tid & 31) == 0) { rs[tid >> 5] = s; rq[tid >> 5] = sq; }
    __syncthreads();
    s  = rs[0] + rs[1] + rs[2] + rs[3];
    sq = rq[0] + rq[1] + rq[2] + rq[3];

    const float mean = s * (1.0f / DD);
    const float var  = sq * (1.0f / DD) - mean * mean;
    const float inv  = rsqrtf(var + 1e-3f);

    float4 g = reinterpret_cast<const float4*>(gamma)[tid];
    float4 b = reinterpret_cast<const float4*>(beta)[tid];
    v.x = (v.x - mean) * inv * g.x + b.x;
    v.y = (v.y - mean) * inv * g.y + b.y;
    v.z = (v.z - mean) * inv * g.z + b.z;
    v.w = (v.w - mean) * inv * g.w + b.w;
    reinterpret_cast<float4*>(row)[tid] = v;
}

// ---------------------------------------------------------------------------
// Tiled sliding-window attention v4: QT=64 queries/block, 128 threads,
// score tile 8x12 (cols tc+16j over KW=192), PV tile 8x4.
// Conflict-free K/V loads (stride 68 == 4 mod 32).
// ---------------------------------------------------------------------------
__global__ __launch_bounds__(128, 1)
void attn_tile_kernel(const float* __restrict__ kqv, float* __restrict__ ctx)
{
    extern __shared__ float sm[];
    float* Ksm = sm;                           // [KW2][KSTR]
    float* Vsm = sm + KW2 * KSTR;              // [KW2][KSTR]
    float* Qsm = sm + 2 * KW2 * KSTR;          // [QT2][KSTR]
    float* Psm = sm;                           // [QT2][PSTR2] overlaps Ksm
                                               // (64*200=12800 <= 192*68=13056)

    const int tid  = threadIdx.x;
    const int tile = blockIdx.x;
    const int h    = blockIdx.y;
    const int b    = blockIdx.z;

    const int t0 = tile * QT2;
    int kbase = t0 - WINW;
    if (kbase < 0) kbase = 0;
    if (kbase > SS - KW2) kbase = SS - KW2;
    const size_t rowBase = (size_t)(b * SS) * D3 + h * HDIM;

    // ---- stage K, V (192 rows), Q (64 rows): coalesced float4 ----
    {
        const int r0 = tid >> 4;               // 0..7
        const int c4 = (tid & 15) << 2;
        #pragma unroll
        for (int r = r0; r < KW2; r += 8) {
            const float* src = kqv + rowBase + (size_t)(kbase + r) * D3;
            *reinterpret_cast<float4*>(Ksm + r * KSTR + c4) =
                *reinterpret_cast<const float4*>(src + c4);
            *reinterpret_cast<float4*>(Vsm + r * KSTR + c4) =
                *reinterpret_cast<const float4*>(src + 2 * DD + c4);
        }
        #pragma unroll
        for (int r = r0; r < QT2; r += 8) {
            const float* src = kqv + rowBase + (size_t)(t0 + r) * D3 + DD;
            *reinterpret_cast<float4*>(Qsm + r * KSTR + c4) =
                *reinterpret_cast<const float4*>(src + c4);
        }
    }
    __syncthreads();

    // ---- scores: thread (tr 0..7, tc 0..15): q-rows {8tr..8tr+7},
    //      k-cols {tc + 16m, m=0..11} ----
    const int tr = tid >> 4;                   // 0..7
    const int tc = tid & 15;                   // 0..15

    float acc[8][12];
    #pragma unroll
    for (int i = 0; i < 8; i++)
        #pragma unroll
        for (int j = 0; j < 12; j++) acc[i][j] = 0.f;

    #pragma unroll
    for (int k4 = 0; k4 < HDIM; k4 += 4) {
        float4 qa[8];
        #pragma unroll
        for (int i = 0; i < 8; i++)
            qa[i] = *reinterpret_cast<const float4*>(Qsm + (tr * 8 + i) * KSTR + k4);
        #pragma unroll
        for (int j = 0; j < 12; j++) {
            float4 kb = *reinterpret_cast<const float4*>(Ksm + (tc + 16 * j) * KSTR + k4);
            #pragma unroll
            for (int i = 0; i < 8; i++) {
                acc[i][j] = fmaf(qa[i].x, kb.x, acc[i][j]);
                acc[i][j] = fmaf(qa[i].y, kb.y, acc[i][j]);
                acc[i][j] = fmaf(qa[i].z, kb.z, acc[i][j]);
                acc[i][j] = fmaf(qa[i].w, kb.w, acc[i][j]);
            }
        }
    }

    // ---- mask + softmax (per row; 16 lanes share a row) ----
    float inv[8];
    #pragma unroll
    for (int i = 0; i < 8; i++) {
        const int s = t0 + tr * 8 + i;
        int start = s - WINW;
        if (start < 0) start = 0;
        if (start > SS - SUBW) start = SS - SUBW;
        const int off = start - kbase;         // valid cols: [off, off+SUBW)

        float mx = -1e30f;
        #pragma unroll
        for (int j = 0; j < 12; j++) {
            const int c = tc + 16 * j;
            float scv = acc[i][j] * 0.125f;
            if (c < off || c >= off + SUBW) scv = -1e30f;
            acc[i][j] = scv;
            mx = fmaxf(mx, scv);
        }
        #pragma unroll
        for (int o = 1; o < 16; o <<= 1)
            mx = fmaxf(mx, __shfl_xor_sync(0xffffffffu, mx, o));

        float sum = 0.f;
        #pragma unroll
        for (int j = 0; j < 12; j++) {
            float e = __expf(acc[i][j] - mx);
            acc[i][j] = e;
            sum += e;
        }
        #pragma unroll
        for (int o = 1; o < 16; o <<= 1)
            sum += __shfl_xor_sync(0xffffffffu, sum, o);
        inv[i] = 1.0f / sum;
    }

    __syncthreads();   // done reading Ksm before P overwrites it

    #pragma unroll
    for (int i = 0; i < 8; i++) {
        float* prow = Psm + (tr * 8 + i) * PSTR2;
        #pragma unroll
        for (int j = 0; j < 12; j++) prow[tc + 16 * j] = acc[i][j] * inv[i];
    }
    __syncthreads();

    // ---- ctx = P(64x192) @ V(192x64): thread = 8 rows x 4 cols ----
    const int orr = tid >> 4;                  // rows {8orr..8orr+7}
    const int oc4 = (tid & 15) << 2;

    float oacc[8][4];
    #pragma unroll
    for (int i = 0; i < 8; i++)
        #pragma unroll
        for (int j = 0; j < 4; j++) oacc[i][j] = 0.f;

    #pragma unroll 4
    for (int k4 = 0; k4 < KW2; k4 += 4) {
        float4 vb[4];
        #pragma unroll
        for (int q = 0; q < 4; q++)
            vb[q] = *reinterpret_cast<const float4*>(Vsm + (k4 + q) * KSTR + oc4);
        #pragma unroll
        for (int i = 0; i < 8; i++) {
            float4 pa = *reinterpret_cast<const float4*>(
                Psm + (orr * 8 + i) * PSTR2 + k4);
            oacc[i][0] = fmaf(pa.x, vb[0].x, oacc[i][0]);
            oacc[i][1] = fmaf(pa.x, vb[0].y, oacc[i][1]);
            oacc[i][2] = fmaf(pa.x, vb[0].z, oacc[i][2]);
            oacc[i][3] = fmaf(pa.x, vb[0].w, oacc[i][3]);
            oacc[i][0] = fmaf(pa.y, vb[1].x, oacc[i][0]);
            oacc[i][1] = fmaf(pa.y, vb[1].y, oacc[i][1]);
            oacc[i][2] = fmaf(pa.y, vb[1].z, oacc[i][2]);
            oacc[i][3] = fmaf(pa.y, vb[1].w, oacc[i][3]);
            oacc[i][0] = fmaf(pa.z, vb[2].x, oacc[i][0]);
            oacc[i][1] = fmaf(pa.z, vb[2].y, oacc[i][1]);
            oacc[i][2] = fmaf(pa.z, vb[2].z, oacc[i][2]);
            oacc[i][3] = fmaf(pa.z, vb[2].w, oacc[i][3]);
            oacc[i][0] = fmaf(pa.w, vb[3].x, oacc[i][0]);
            oacc[i][1] = fmaf(pa.w, vb[3].y, oacc[i][1]);
            oacc[i][2] = fmaf(pa.w, vb[3].z, oacc[i][2]);
            oacc[i][3] = fmaf(pa.w, vb[3].w, oacc[i][3]);
        }
    }

    #pragma unroll
    for (int i = 0; i < 8; i++) {
        float* dst = ctx + (size_t)(b * SS + t0 + orr * 8 + i) * DD + h * HDIM + oc4;
        float4 o;
        o.x = rtf32(oacc[i][0]); o.y = rtf32(oacc[i][1]);
        o.z = rtf32(oacc[i][2]); o.w = rtf32(oacc[i][3]);
        *reinterpret_cast<float4*>(dst) = o;
    }
}

// ---------------------------------------------------------------------------
extern "C" void kernel_launch(void* const* d_in, const int* in_sizes, int n_in,
                              void* d_out, int out_size)
{
    const float* values   = (const float*)d_in[0];
    const float* W_kqv    = (const float*)d_in[1];
    const float* b_kqv    = (const float*)d_in[2];
    const float* ln_gamma = (const float*)d_in[3];
    const float* ln_beta  = (const float*)d_in[4];
    const float* W_kernel = (const float*)d_in[5];
    const float* b_kernel = (const float*)d_in[6];
    const float* W_proj   = (const float*)d_in[7];
    const float* b_proj   = (const float*)d_in[8];
    float* out = (float*)d_out;

    float *kqv, *ctx, *x1, *va, *wq, *wk, *wp, *ps;
    cudaGetSymbolAddress((void**)&kqv, g_kqv);
    cudaGetSymbolAddress((void**)&ctx, g_ctx);
    cudaGetSymbolAddress((void**)&x1,  g_x1);
    cudaGetSymbolAddress((void**)&va,  g_va);
    cudaGetSymbolAddress((void**)&wq,  g_wq);
    cudaGetSymbolAddress((void**)&wk,  g_wk);
    cudaGetSymbolAddress((void**)&wp,  g_wp);
    cudaGetSymbolAddress((void**)&ps,  g_ps);

    const int attnSmem = (2 * KW2 * KSTR + QT2 * KSTR) * sizeof(float);  // 121856

    static bool attrSet = false;
    if (!attrSet) {
        cudaFuncSetAttribute(attn_tile_kernel,
                             cudaFuncAttributeMaxDynamicSharedMemorySize, attnSmem);
        cudaFuncSetAttribute(tgemm_k<0>,
                             cudaFuncAttributeMaxDynamicSharedMemorySize, GEMM_SMEM);
        cudaFuncSetAttribute(tgemm_k<1>,
                             cudaFuncAttributeMaxDynamicSharedMemorySize, GEMM_SMEM);
        cudaFuncSetAttribute(tgemm_k<3>,
                             cudaFuncAttributeMaxDynamicSharedMemorySize, GEMM_SMEM);
        attrSet = true;
    }

    // 0) one fused tf32 rounding pass over values + all weights
    tf32_round_all<<<R_WP / 256, 256>>>(values, W_kqv, W_kernel, W_proj,
                                        va, wq, wk, wp);

    // 1) kqv = values @ W_kqv + b_kqv   (grid 12x32)
    tgemm_k<0><<<dim3(D3 / 128, TT / 128), 128, GEMM_SMEM>>>(
        va, wq, b_kqv, kqv, TT, D3, DD, DD);

    // 2) LayerNorm q and k in place
    ln_kernel<<<dim3(TT, 2), 128>>>(kqv, ln_gamma, ln_beta);

    // 3) attention (QT=64 tiles) -> ctx (tf32-rounded)
    attn_tile_kernel<<<dim3(SS / QT2, HH, BB), 128, attnSmem>>>(kqv, ctx);

    // 4) x1 = relu(ctx @ W_kernel + b_kernel)   (grid 16x32)
    tgemm_k<1><<<dim3(KSZ / 128, TT / 128), 128, GEMM_SMEM>>>(
        ctx, wk, b_kernel, x1, TT, KSZ, DD, DD);

    // 5a) split-K=2 proj partials (grid 4x32x2 = 256 blocks)
    tgemm_k<3><<<dim3(DD / 128, TT / 128, 2), 128, GEMM_SMEM>>>(
        x1, wp, nullptr, ps, TT, DD, KSZ / 2, KSZ);

    // 5b) out = ps0 + ps1 + b_proj + v
    splitk_reduce<<<(TT * DD / 4) / 256, 256>>>(ps, b_proj, kqv, out);
}

// round 17
// speedup vs baseline: 1.2394x; 1.2394x over previous
#include <cuda_runtime.h>
#include <mma.h>
#include <math.h>
#include <stdint.h>

using namespace nvcuda;

// Problem constants
#define BB   2
#define SS   2048
#define HH   8
#define HDIM 64
#define DD   512
#define WINW 64
#define SUBW 129
#define KSZ  2048
#define TT   (BB*SS)          // 4096
#define D3   (3*DD)           // 1536

// Attention tile constants (round-7 proven)
#define QT   32
#define KW   160
#define KSTR 68
#define PSTR 168

// GEMM tile constants (128x128 block, BK=32, 4 warps, warp tile 64x64)
#define BKG   32
#define ASTR  36
#define BSTR  132
#define CSTR  132
#define AS_FLOATS (128 * ASTR)           // 4608
#define BS_FLOATS (BKG * BSTR)           // 4224
#define GEMM_SMEM ((2 * AS_FLOATS + 2 * BS_FLOATS) * 4)   // 70656 B

// Scratch (device globals; allocation-free)
__device__ float g_kqv[TT * D3];
__device__ float g_ctx[TT * DD];
__device__ float g_x1 [TT * KSZ];
__device__ float g_va [TT * DD];
__device__ float g_wq [DD * D3];
__device__ float g_wk [DD * KSZ];
__device__ float g_wp [KSZ * DD];
__device__ float g_ps [2 * TT * DD];     // split-K partials for proj GEMM

// ---------------------------------------------------------------------------
__device__ __forceinline__ float rtf32(float x) {
    uint32_t u;
    asm("cvt.rna.tf32.f32 %0, %1;" : "=r"(u) : "f"(x));
    return __uint_as_float(u);
}

#define CP_ASYNC16(dst_u32, src_ptr) \
    asm volatile("cp.async.cg.shared.global [%0], [%1], 16;" \
                 :: "r"(dst_u32), "l"(src_ptr))
#define CP_COMMIT()  asm volatile("cp.async.commit_group;")
#define CP_WAIT0()   asm volatile("cp.async.wait_group 0;")
#define CP_WAIT1()   asm volatile("cp.async.wait_group 1;")

// ---------------------------------------------------------------------------
// tf32 wmma GEMM: 128x128 block, 4 warps, warp tile 64x64 (4x4 frags),
// BK=32, cp.async double-buffered, occupancy 2.  (round-14 proven config)
// EPI: 0 = bias ; 1 = bias+relu (tf32 out) ; 3 = raw split-K partial
// ---------------------------------------------------------------------------
template <int EPI>
__global__ __launch_bounds__(128, 2)
void tgemm_k(const float* __restrict__ A, const float* __restrict__ Bm,
             const float* __restrict__ bias,
             float* __restrict__ C, int M, int N, int K, int lda)
{
    extern __shared__ float sm[];
    const uint32_t sbase = (uint32_t)__cvta_generic_to_shared(sm);

    const int tid    = threadIdx.x;
    const int warpId = tid >> 5;
    const int warpM  = warpId & 1;
    const int warpN  = warpId >> 1;

    const int blockN = blockIdx.x * 128;
    const int blockM = blockIdx.y * 128;
    const int kOff   = blockIdx.z * K;
    float* Cz = (EPI == 3) ? C + (size_t)blockIdx.z * M * N : C;

    wmma::fragment<wmma::accumulator, 16, 16, 8, float> acc[4][4];
    #pragma unroll
    for (int i = 0; i < 4; i++)
        #pragma unroll
        for (int j = 0; j < 4; j++) wmma::fill_fragment(acc[i][j], 0.f);

    auto loadTile = [&](int k0, int buf) {
        const uint32_t aOff = buf * AS_FLOATS;
        const uint32_t bOff = 2 * AS_FLOATS + buf * BS_FLOATS;
        #pragma unroll
        for (int p = 0; p < 8; p++) {
            const int idx = p * 128 + tid;
            const int ar  = idx >> 3;
            const int ac4 = (idx & 7) << 2;
            CP_ASYNC16(sbase + (aOff + ar * ASTR + ac4) * 4,
                       A + (size_t)(blockM + ar) * lda + kOff + k0 + ac4);
            const int br  = idx >> 5;
            const int bc4 = (idx & 31) << 2;
            CP_ASYNC16(sbase + (bOff + br * BSTR + bc4) * 4,
                       Bm + (size_t)(kOff + k0 + br) * N + blockN + bc4);
        }
    };

    const int nIter = K / BKG;
    loadTile(0, 0);
    CP_COMMIT();

    for (int i = 0; i < nIter; i++) {
        const int buf = i & 1;
        if (i + 1 < nIter) {
            loadTile((i + 1) * BKG, buf ^ 1);
            CP_COMMIT();
            CP_WAIT1();
        } else {
            CP_WAIT0();
        }
        __syncthreads();

        const float* As = sm + buf * AS_FLOATS;
        const float* Bs = sm + 2 * AS_FLOATS + buf * BS_FLOATS;
        #pragma unroll
        for (int kk = 0; kk < BKG; kk += 8) {
            wmma::fragment<wmma::matrix_a, 16, 16, 8, wmma::precision::tf32, wmma::row_major> af[4];
            wmma::fragment<wmma::matrix_b, 16, 16, 8, wmma::precision::tf32, wmma::row_major> bf[4];
            #pragma unroll
            for (int ii = 0; ii < 4; ii++)
                wmma::load_matrix_sync(af[ii],
                    As + (warpM * 64 + ii * 16) * ASTR + kk, ASTR);
            #pragma unroll
            for (int j = 0; j < 4; j++)
                wmma::load_matrix_sync(bf[j],
                    Bs + kk * BSTR + warpN * 64 + j * 16, BSTR);
            #pragma unroll
            for (int ii = 0; ii < 4; ii++)
                #pragma unroll
                for (int j = 0; j < 4; j++)
                    wmma::mma_sync(acc[ii][j], af[ii], bf[j], acc[ii][j]);
        }
        __syncthreads();
    }

    // epilogue: stage full 128x128 C tile through smem
    #pragma unroll
    for (int ii = 0; ii < 4; ii++)
        #pragma unroll
        for (int j = 0; j < 4; j++)
            wmma::store_matrix_sync(
                sm + (warpM * 64 + ii * 16) * CSTR + warpN * 64 + j * 16,
                acc[ii][j], CSTR, wmma::mem_row_major);
    __syncthreads();

    const int ec4 = (tid & 31) << 2;
    const int er0 = tid >> 5;
    float4 bi = make_float4(0.f, 0.f, 0.f, 0.f);
    if (EPI != 3)
        bi = *reinterpret_cast<const float4*>(bias + blockN + ec4);
    #pragma unroll
    for (int p = 0; p < 32; p++) {
        const int r = p * 4 + er0;
        const int grow = blockM + r;
        float4 o = *reinterpret_cast<const float4*>(sm + r * CSTR + ec4);
        o.x += bi.x; o.y += bi.y; o.z += bi.z; o.w += bi.w;
        if (EPI == 1) {
            o.x = rtf32(fmaxf(o.x, 0.f)); o.y = rtf32(fmaxf(o.y, 0.f));
            o.z = rtf32(fmaxf(o.z, 0.f)); o.w = rtf32(fmaxf(o.w, 0.f));
        }
        *reinterpret_cast<float4*>(&Cz[(size_t)grow * N + blockN + ec4]) = o;
    }
}

// ---------------------------------------------------------------------------
// Split-K reduction: out = ps[0] + ps[1] + b_proj + v
// ---------------------------------------------------------------------------
__global__ void splitk_reduce(const float* __restrict__ ps,
                              const float* __restrict__ bias,
                              const float* __restrict__ kqv,
                              float* __restrict__ out)
{
    const int i = blockIdx.x * blockDim.x + threadIdx.x;
    const int row = i / (DD / 4);
    const int c4  = (i % (DD / 4)) * 4;

    float4 a = reinterpret_cast<const float4*>(ps)[i];
    float4 b = reinterpret_cast<const float4*>(ps + (size_t)TT * DD)[i];
    float4 bi = *reinterpret_cast<const float4*>(bias + c4);
    float4 v = *reinterpret_cast<const float4*>(
        kqv + (size_t)row * D3 + 2 * DD + c4);

    float4 o;
    o.x = a.x + b.x + bi.x + v.x;
    o.y = a.y + b.y + bi.y + v.y;
    o.z = a.z + b.z + bi.z + v.z;
    o.w = a.w + b.w + bi.w + v.w;
    reinterpret_cast<float4*>(out)[i] = o;
}

// ---------------------------------------------------------------------------
// Fused tf32 rounding of all four source tensors in one launch.
// ---------------------------------------------------------------------------
#define R_VA 524288
#define R_WQ (R_VA + 196608)
#define R_WK (R_WQ + 262144)
#define R_WP (R_WK + 262144)

__global__ void tf32_round_all(const float* __restrict__ values,
                               const float* __restrict__ Wq,
                               const float* __restrict__ Wk,
                               const float* __restrict__ Wp,
                               float* __restrict__ va, float* __restrict__ wq,
                               float* __restrict__ wk, float* __restrict__ wp)
{
    const int i = blockIdx.x * blockDim.x + threadIdx.x;
    const float4* src; float4* dst; int off;
    if (i < R_VA)      { src = (const float4*)values; dst = (float4*)va; off = i; }
    else if (i < R_WQ) { src = (const float4*)Wq;     dst = (float4*)wq; off = i - R_VA; }
    else if (i < R_WK) { src = (const float4*)Wk;     dst = (float4*)wk; off = i - R_WQ; }
    else               { src = (const float4*)Wp;     dst = (float4*)wp; off = i - R_WK; }
    float4 v = src[off];
    v.x = rtf32(v.x); v.y = rtf32(v.y); v.z = rtf32(v.z); v.w = rtf32(v.w);
    dst[off] = v;
}

// ---------------------------------------------------------------------------
// LayerNorm: one block per token, 256 threads; warps 0-3 normalize the
// k half (cols 0..511), warps 4-7 the q half (cols 512..1023).
// Independent 4-warp reductions per half.
// ---------------------------------------------------------------------------
__global__ void ln_kernel(float* __restrict__ kqv,
                          const float* __restrict__ gamma,
                          const float* __restrict__ beta)
{
    const int t   = blockIdx.x;
    const int sel = threadIdx.x >> 7;         // 0 = k-half, 1 = q-half
    const int tid = threadIdx.x & 127;        // 0..127 within half
    float* row = kqv + (size_t)t * D3 + sel * DD;

    float4 v = reinterpret_cast<float4*>(row)[tid];
    float s  = v.x + v.y + v.z + v.w;
    float sq = v.x*v.x + v.y*v.y + v.z*v.z + v.w*v.w;

    #pragma unroll
    for (int o = 16; o; o >>= 1) {
        s  += __shfl_xor_sync(0xffffffffu, s,  o);
        sq += __shfl_xor_sync(0xffffffffu, sq, o);
    }
    __shared__ float rs[2][4], rq[2][4];
    if ((tid & 31) == 0) { rs[sel][tid >> 5] = s; rq[sel][tid >> 5] = sq; }
    __syncthreads();
    s  = rs[sel][0] + rs[sel][1] + rs[sel][2] + rs[sel][3];
    sq = rq[sel][0] + rq[sel][1] + rq[sel][2] + rq[sel][3];

    const float mean = s * (1.0f / DD);
    const float var  = sq * (1.0f / DD) - mean * mean;
    const float inv  = rsqrtf(var + 1e-3f);

    float4 g = reinterpret_cast<const float4*>(gamma)[tid];
    float4 b = reinterpret_cast<const float4*>(beta)[tid];
    v.x = (v.x - mean) * inv * g.x + b.x;
    v.y = (v.y - mean) * inv * g.y + b.y;
    v.z = (v.z - mean) * inv * g.z + b.z;
    v.w = (v.w - mean) * inv * g.w + b.w;
    reinterpret_cast<float4*>(row)[tid] = v;
}

// ---------------------------------------------------------------------------
// Tiled sliding-window attention (round-7 proven config: 128 threads,
// 4x10 score tile, stride-16 conflict-free mapping, 4x4 PV tile).
// ---------------------------------------------------------------------------
__global__ __launch_bounds__(128, 2)
void attn_tile_kernel(const float* __restrict__ kqv, float* __restrict__ ctx)
{
    extern __shared__ float sm[];
    float* Ksm = sm;
    float* Vsm = sm + KW * KSTR;
    float* Qsm = sm + 2 * KW * KSTR;
    float* Psm = sm;

    const int tid  = threadIdx.x;
    const int tile = blockIdx.x;
    const int h    = blockIdx.y;
    const int b    = blockIdx.z;

    const int t0 = tile * QT;
    int kbase = t0 - WINW;
    if (kbase < 0) kbase = 0;
    if (kbase > SS - KW) kbase = SS - KW;
    const size_t rowBase = (size_t)(b * SS) * D3 + h * HDIM;

    {
        const int r0 = tid >> 4;
        const int c4 = (tid & 15) << 2;
        #pragma unroll
        for (int r = r0; r < KW; r += 8) {
            const float* src = kqv + rowBase + (size_t)(kbase + r) * D3;
            *reinterpret_cast<float4*>(Ksm + r * KSTR + c4) =
                *reinterpret_cast<const float4*>(src + c4);
            *reinterpret_cast<float4*>(Vsm + r * KSTR + c4) =
                *reinterpret_cast<const float4*>(src + 2 * DD + c4);
        }
        #pragma unroll
        for (int r = r0; r < QT; r += 8) {
            const float* src = kqv + rowBase + (size_t)(t0 + r) * D3 + DD;
            *reinterpret_cast<float4*>(Qsm + r * KSTR + c4) =
                *reinterpret_cast<const float4*>(src + c4);
        }
    }
    __syncthreads();

    const int tr = tid >> 4;
    const int tc = tid & 15;

    float acc[4][10];
    #pragma unroll
    for (int i = 0; i < 4; i++)
        #pragma unroll
        for (int j = 0; j < 10; j++) acc[i][j] = 0.f;

    #pragma unroll
    for (int k4 = 0; k4 < HDIM; k4 += 4) {
        float4 qa[4];
        #pragma unroll
        for (int i = 0; i < 4; i++)
            qa[i] = *reinterpret_cast<const float4*>(Qsm + (tr * 4 + i) * KSTR + k4);
        #pragma unroll
        for (int j = 0; j < 10; j++) {
            float4 kb = *reinterpret_cast<const float4*>(Ksm + (tc + 16 * j) * KSTR + k4);
            #pragma unroll
            for (int i = 0; i < 4; i++) {
                acc[i][j] = fmaf(qa[i].x, kb.x, acc[i][j]);
                acc[i][j] = fmaf(qa[i].y, kb.y, acc[i][j]);
                acc[i][j] = fmaf(qa[i].z, kb.z, acc[i][j]);
                acc[i][j] = fmaf(qa[i].w, kb.w, acc[i][j]);
            }
        }
    }

    float inv[4];
    #pragma unroll
    for (int i = 0; i < 4; i++) {
        const int s = t0 + tr * 4 + i;
        int start = s - WINW;
        if (start < 0) start = 0;
        if (start > SS - SUBW) start = SS - SUBW;
        const int off = start - kbase;

        float mx = -1e30f;
        #pragma unroll
        for (int j = 0; j < 10; j++) {
            const int c = tc + 16 * j;
            float scv = acc[i][j] * 0.125f;
            if (c < off || c >= off + SUBW) scv = -1e30f;
            acc[i][j] = scv;
            mx = fmaxf(mx, scv);
        }
        #pragma unroll
        for (int o = 1; o < 16; o <<= 1)
            mx = fmaxf(mx, __shfl_xor_sync(0xffffffffu, mx, o));

        float sum = 0.f;
        #pragma unroll
        for (int j = 0; j < 10; j++) {
            float e = __expf(acc[i][j] - mx);
            acc[i][j] = e;
            sum += e;
        }
        #pragma unroll
        for (int o = 1; o < 16; o <<= 1)
            sum += __shfl_xor_sync(0xffffffffu, sum, o);
        inv[i] = 1.0f / sum;
    }

    __syncthreads();

    #pragma unroll
    for (int i = 0; i < 4; i++) {
        float* prow = Psm + (tr * 4 + i) * PSTR;
        #pragma unroll
        for (int j = 0; j < 10; j++) prow[tc + 16 * j] = acc[i][j] * inv[i];
    }
    __syncthreads();

    const int orr = tid >> 4;
    const int oc4 = (tid & 15) << 2;

    float oacc[4][4];
    #pragma unroll
    for (int i = 0; i < 4; i++)
        #pragma unroll
        for (int j = 0; j < 4; j++) oacc[i][j] = 0.f;

    #pragma unroll 5
    for (int k4 = 0; k4 < KW; k4 += 4) {
        float4 pa[4];
        #pragma unroll
        for (int i = 0; i < 4; i++)
            pa[i] = *reinterpret_cast<const float4*>(Psm + (orr * 4 + i) * PSTR + k4);
        float4 vb[4];
        #pragma unroll
        for (int q = 0; q < 4; q++)
            vb[q] = *reinterpret_cast<const float4*>(Vsm + (k4 + q) * KSTR + oc4);

        #pragma unroll
        for (int i = 0; i < 4; i++) {
            oacc[i][0] = fmaf(pa[i].x, vb[0].x, oacc[i][0]);
            oacc[i][1] = fmaf(pa[i].x, vb[0].y, oacc[i][1]);
            oacc[i][2] = fmaf(pa[i].x, vb[0].z, oacc[i][2]);
            oacc[i][3] = fmaf(pa[i].x, vb[0].w, oacc[i][3]);
            oacc[i][0] = fmaf(pa[i].y, vb[1].x, oacc[i][0]);
            oacc[i][1] = fmaf(pa[i].y, vb[1].y, oacc[i][1]);
            oacc[i][2] = fmaf(pa[i].y, vb[1].z, oacc[i][2]);
            oacc[i][3] = fmaf(pa[i].y, vb[1].w, oacc[i][3]);
            oacc[i][0] = fmaf(pa[i].z, vb[2].x, oacc[i][0]);
            oacc[i][1] = fmaf(pa[i].z, vb[2].y, oacc[i][1]);
            oacc[i][2] = fmaf(pa[i].z, vb[2].z, oacc[i][2]);
            oacc[i][3] = fmaf(pa[i].z, vb[2].w, oacc[i][3]);
            oacc[i][0] = fmaf(pa[i].w, vb[3].x, oacc[i][0]);
            oacc[i][1] = fmaf(pa[i].w, vb[3].y, oacc[i][1]);
            oacc[i][2] = fmaf(pa[i].w, vb[3].z, oacc[i][2]);
            oacc[i][3] = fmaf(pa[i].w, vb[3].w, oacc[i][3]);
        }
    }

    #pragma unroll
    for (int i = 0; i < 4; i++) {
        float* dst = ctx + (size_t)(b * SS + t0 + orr * 4 + i) * DD + h * HDIM + oc4;
        float4 o;
        o.x = rtf32(oacc[i][0]); o.y = rtf32(oacc[i][1]);
        o.z = rtf32(oacc[i][2]); o.w = rtf32(oacc[i][3]);
        *reinterpret_cast<float4*>(dst) = o;
    }
}

// ---------------------------------------------------------------------------
extern "C" void kernel_launch(void* const* d_in, const int* in_sizes, int n_in,
                              void* d_out, int out_size)
{
    const float* values   = (const float*)d_in[0];
    const float* W_kqv    = (const float*)d_in[1];
    const float* b_kqv    = (const float*)d_in[2];
    const float* ln_gamma = (const float*)d_in[3];
    const float* ln_beta  = (const float*)d_in[4];
    const float* W_kernel = (const float*)d_in[5];
    const float* b_kernel = (const float*)d_in[6];
    const float* W_proj   = (const float*)d_in[7];
    const float* b_proj   = (const float*)d_in[8];
    float* out = (float*)d_out;

    float *kqv, *ctx, *x1, *va, *wq, *wk, *wp, *ps;
    cudaGetSymbolAddress((void**)&kqv, g_kqv);
    cudaGetSymbolAddress((void**)&ctx, g_ctx);
    cudaGetSymbolAddress((void**)&x1,  g_x1);
    cudaGetSymbolAddress((void**)&va,  g_va);
    cudaGetSymbolAddress((void**)&wq,  g_wq);
    cudaGetSymbolAddress((void**)&wk,  g_wk);
    cudaGetSymbolAddress((void**)&wp,  g_wp);
    cudaGetSymbolAddress((void**)&ps,  g_ps);

    const int attnSmem = (2 * KW * KSTR + QT * KSTR) * sizeof(float);

    static bool attrSet = false;
    if (!attrSet) {
        cudaFuncSetAttribute(attn_tile_kernel,
                             cudaFuncAttributeMaxDynamicSharedMemorySize, attnSmem);
        cudaFuncSetAttribute(tgemm_k<0>,
                             cudaFuncAttributeMaxDynamicSharedMemorySize, GEMM_SMEM);
        cudaFuncSetAttribute(tgemm_k<1>,
                             cudaFuncAttributeMaxDynamicSharedMemorySize, GEMM_SMEM);
        cudaFuncSetAttribute(tgemm_k<3>,
                             cudaFuncAttributeMaxDynamicSharedMemorySize, GEMM_SMEM);
        attrSet = true;
    }

    // 0) one fused tf32 rounding pass over values + all weights
    tf32_round_all<<<R_WP / 256, 256>>>(values, W_kqv, W_kernel, W_proj,
                                        va, wq, wk, wp);

    // 1) kqv = values @ W_kqv + b_kqv   (grid 12x32)
    tgemm_k<0><<<dim3(D3 / 128, TT / 128), 128, GEMM_SMEM>>>(
        va, wq, b_kqv, kqv, TT, D3, DD, DD);

    // 2) LayerNorm q and k (one block per token, 256 threads)
    ln_kernel<<<TT, 256>>>(kqv, ln_gamma, ln_beta);

    // 3) attention -> ctx (tf32-rounded)
    attn_tile_kernel<<<dim3(SS / QT, HH, BB), 128, attnSmem>>>(kqv, ctx);

    // 4) x1 = relu(ctx @ W_kernel + b_kernel)   (grid 16x32)
    tgemm_k<1><<<dim3(KSZ / 128, TT / 128), 128, GEMM_SMEM>>>(
        ctx, wk, b_kernel, x1, TT, KSZ, DD, DD);

    // 5a) split-K=2 proj partials (grid 4x32x2 = 256 blocks)
    tgemm_k<3><<<dim3(DD / 128, TT / 128, 2), 128, GEMM_SMEM>>>(
        x1, wp, nullptr, ps, TT, DD, KSZ / 2, KSZ);

    // 5b) out = ps0 + ps1 + b_proj + v
    splitk_reduce<<<(TT * DD / 4) / 256, 256>>>(ps, b_proj, kqv, out);
}